// round 12
// baseline (speedup 1.0000x reference)
#include <cuda_runtime.h>
#include <cstdint>

// RowSoftmax over edges:
//   et  = exp(leaky_relu(attr, 0.01))
//   out = et / segment_sum(et, row)
//
// edge_index is int32 on device (JAX x64 disabled). d_in[0] = (2,E) int32,
// row = first E entries.
//
// Perf model (B300): normalize is L1tex gather-bound, scatter is REDG
// spread-addr bound. Both benefit from deep MLP; this round 16 edges/thread.

#define N_NODES 1000000

__device__ float g_rowsum[N_NODES];  // 4 MB, L2-resident during hot passes

__global__ void zero_rowsum_kernel() {
    int i = blockIdx.x * blockDim.x + threadIdx.x;
    if (i < N_NODES / 4) {
        reinterpret_cast<float4*>(g_rowsum)[i] = make_float4(0.f, 0.f, 0.f, 0.f);
    }
}

__device__ __forceinline__ float et_of(float a) {
    float lr = a > 0.0f ? a : 0.01f * a;
    return __expf(lr);
}

// Pass A: et = exp(lrelu(attr)); out = et; g_rowsum[row] += et. 16 edges/thread.
__global__ void scatter_kernel(const int* __restrict__ row,
                               const float* __restrict__ attr,
                               float* __restrict__ out,
                               int E) {
    int t = blockIdx.x * blockDim.x + threadIdx.x;
    int e = t * 16;
    if (e + 15 < E) {
        // Front-batch all global loads for MLP
        float4 a0 = *reinterpret_cast<const float4*>(attr + e);
        float4 a1 = *reinterpret_cast<const float4*>(attr + e + 4);
        float4 a2 = *reinterpret_cast<const float4*>(attr + e + 8);
        float4 a3 = *reinterpret_cast<const float4*>(attr + e + 12);
        int4   r0 = *reinterpret_cast<const int4*>(row + e);
        int4   r1 = *reinterpret_cast<const int4*>(row + e + 4);
        int4   r2 = *reinterpret_cast<const int4*>(row + e + 8);
        int4   r3 = *reinterpret_cast<const int4*>(row + e + 12);

        float e0  = et_of(a0.x), e1  = et_of(a0.y), e2  = et_of(a0.z), e3  = et_of(a0.w);
        float e4  = et_of(a1.x), e5  = et_of(a1.y), e6  = et_of(a1.z), e7  = et_of(a1.w);
        float e8  = et_of(a2.x), e9  = et_of(a2.y), e10 = et_of(a2.z), e11 = et_of(a2.w);
        float e12 = et_of(a3.x), e13 = et_of(a3.y), e14 = et_of(a3.z), e15 = et_of(a3.w);

        *reinterpret_cast<float4*>(out + e)      = make_float4(e0,  e1,  e2,  e3);
        *reinterpret_cast<float4*>(out + e + 4)  = make_float4(e4,  e5,  e6,  e7);
        *reinterpret_cast<float4*>(out + e + 8)  = make_float4(e8,  e9,  e10, e11);
        *reinterpret_cast<float4*>(out + e + 12) = make_float4(e12, e13, e14, e15);

        atomicAdd(&g_rowsum[r0.x], e0);
        atomicAdd(&g_rowsum[r0.y], e1);
        atomicAdd(&g_rowsum[r0.z], e2);
        atomicAdd(&g_rowsum[r0.w], e3);
        atomicAdd(&g_rowsum[r1.x], e4);
        atomicAdd(&g_rowsum[r1.y], e5);
        atomicAdd(&g_rowsum[r1.z], e6);
        atomicAdd(&g_rowsum[r1.w], e7);
        atomicAdd(&g_rowsum[r2.x], e8);
        atomicAdd(&g_rowsum[r2.y], e9);
        atomicAdd(&g_rowsum[r2.z], e10);
        atomicAdd(&g_rowsum[r2.w], e11);
        atomicAdd(&g_rowsum[r3.x], e12);
        atomicAdd(&g_rowsum[r3.y], e13);
        atomicAdd(&g_rowsum[r3.z], e14);
        atomicAdd(&g_rowsum[r3.w], e15);
    } else {
        for (int k = e; k < E; k++) {
            float lr = attr[k] > 0.0f ? attr[k] : 0.01f * attr[k];
            float ek = expf(lr);
            out[k] = ek;
            atomicAdd(&g_rowsum[row[k]], ek);
        }
    }
}

// Invert sums in place.
__global__ void recip_kernel() {
    int i = blockIdx.x * blockDim.x + threadIdx.x;
    if (i < N_NODES) g_rowsum[i] = 1.0f / g_rowsum[i];
}

// Pass B: out[e] *= rinv[row[e]]. 16 edges/thread, front-batched loads.
__global__ void normalize_kernel(const int* __restrict__ row,
                                 float* __restrict__ out,
                                 int E) {
    int t = blockIdx.x * blockDim.x + threadIdx.x;
    int e = t * 16;
    if (e + 15 < E) {
        int4 r0 = *reinterpret_cast<const int4*>(row + e);
        int4 r1 = *reinterpret_cast<const int4*>(row + e + 4);
        int4 r2 = *reinterpret_cast<const int4*>(row + e + 8);
        int4 r3 = *reinterpret_cast<const int4*>(row + e + 12);
        float4 v0 = *reinterpret_cast<const float4*>(out + e);
        float4 v1 = *reinterpret_cast<const float4*>(out + e + 4);
        float4 v2 = *reinterpret_cast<const float4*>(out + e + 8);
        float4 v3 = *reinterpret_cast<const float4*>(out + e + 12);

        float s0  = g_rowsum[r0.x];
        float s1  = g_rowsum[r0.y];
        float s2  = g_rowsum[r0.z];
        float s3  = g_rowsum[r0.w];
        float s4  = g_rowsum[r1.x];
        float s5  = g_rowsum[r1.y];
        float s6  = g_rowsum[r1.z];
        float s7  = g_rowsum[r1.w];
        float s8  = g_rowsum[r2.x];
        float s9  = g_rowsum[r2.y];
        float s10 = g_rowsum[r2.z];
        float s11 = g_rowsum[r2.w];
        float s12 = g_rowsum[r3.x];
        float s13 = g_rowsum[r3.y];
        float s14 = g_rowsum[r3.z];
        float s15 = g_rowsum[r3.w];

        v0.x *= s0;  v0.y *= s1;  v0.z *= s2;  v0.w *= s3;
        v1.x *= s4;  v1.y *= s5;  v1.z *= s6;  v1.w *= s7;
        v2.x *= s8;  v2.y *= s9;  v2.z *= s10; v2.w *= s11;
        v3.x *= s12; v3.y *= s13; v3.z *= s14; v3.w *= s15;

        *reinterpret_cast<float4*>(out + e)      = v0;
        *reinterpret_cast<float4*>(out + e + 4)  = v1;
        *reinterpret_cast<float4*>(out + e + 8)  = v2;
        *reinterpret_cast<float4*>(out + e + 12) = v3;
    } else {
        for (int k = e; k < E; k++) {
            out[k] *= g_rowsum[row[k]];
        }
    }
}

extern "C" void kernel_launch(void* const* d_in, const int* in_sizes, int n_in,
                              void* d_out, int out_size) {
    const int*   row  = (const int*)d_in[0];   // first E of (2,E) int32
    const float* attr = (const float*)d_in[1];
    float*       out  = (float*)d_out;
    int E = in_sizes[1];

    const int T = 256;
    zero_rowsum_kernel<<<(N_NODES / 4 + T - 1) / T, T>>>();

    int e16 = (E + 15) / 16;
    int eblk = (e16 + T - 1) / T;
    scatter_kernel<<<eblk, T>>>(row, attr, out, E);

    recip_kernel<<<(N_NODES + T - 1) / T, T>>>();

    normalize_kernel<<<eblk, T>>>(row, out, E);
}

// round 14
// speedup vs baseline: 1.0823x; 1.0823x over previous
#include <cuda_runtime.h>
#include <cstdint>

// RowSoftmax over edges:
//   et  = exp(leaky_relu(attr, 0.01))
//   out = et / segment_sum(et, row)
//
// edge_index is int32 on device (JAX x64 disabled). d_in[0] = (2,E) int32,
// row = first E entries.
//
// Perf model (B300): normalize is L1tex gather-bound, scatter REDG-bound.
// R12 lesson: 16/thread kills occupancy; 8/thread optimal. This round:
// evict-first (.cs) policy on all streaming traffic so the 4MB g_rowsum
// array keeps L2 residency against 384MB/pass of single-use stream data.

#define N_NODES 1000000

__device__ float g_rowsum[N_NODES];  // 4 MB, L2-resident during hot passes

__global__ void zero_rowsum_kernel() {
    int i = blockIdx.x * blockDim.x + threadIdx.x;
    if (i < N_NODES / 4) {
        reinterpret_cast<float4*>(g_rowsum)[i] = make_float4(0.f, 0.f, 0.f, 0.f);
    }
}

__device__ __forceinline__ float et_of(float a) {
    float lr = a > 0.0f ? a : 0.01f * a;
    return __expf(lr);
}

// Pass A: et = exp(lrelu(attr)); out = et; g_rowsum[row] += et. 8 edges/thread.
__global__ void scatter_kernel(const int* __restrict__ row,
                               const float* __restrict__ attr,
                               float* __restrict__ out,
                               int E) {
    int t = blockIdx.x * blockDim.x + threadIdx.x;
    int e = t * 8;
    if (e + 7 < E) {
        // Front-batch streaming loads (evict-first: single-use data)
        float4 a0 = __ldcs(reinterpret_cast<const float4*>(attr + e));
        float4 a1 = __ldcs(reinterpret_cast<const float4*>(attr + e + 4));
        int4   r0 = __ldcs(reinterpret_cast<const int4*>(row + e));
        int4   r1 = __ldcs(reinterpret_cast<const int4*>(row + e + 4));

        float e0 = et_of(a0.x), e1 = et_of(a0.y), e2 = et_of(a0.z), e3 = et_of(a0.w);
        float e4 = et_of(a1.x), e5 = et_of(a1.y), e6 = et_of(a1.z), e7 = et_of(a1.w);

        __stcs(reinterpret_cast<float4*>(out + e),     make_float4(e0, e1, e2, e3));
        __stcs(reinterpret_cast<float4*>(out + e + 4), make_float4(e4, e5, e6, e7));

        atomicAdd(&g_rowsum[r0.x], e0);
        atomicAdd(&g_rowsum[r0.y], e1);
        atomicAdd(&g_rowsum[r0.z], e2);
        atomicAdd(&g_rowsum[r0.w], e3);
        atomicAdd(&g_rowsum[r1.x], e4);
        atomicAdd(&g_rowsum[r1.y], e5);
        atomicAdd(&g_rowsum[r1.z], e6);
        atomicAdd(&g_rowsum[r1.w], e7);
    } else {
        for (int k = e; k < E; k++) {
            float lr = attr[k] > 0.0f ? attr[k] : 0.01f * attr[k];
            float ek = expf(lr);
            out[k] = ek;
            atomicAdd(&g_rowsum[row[k]], ek);
        }
    }
}

// Invert sums in place.
__global__ void recip_kernel() {
    int i = blockIdx.x * blockDim.x + threadIdx.x;
    if (i < N_NODES) g_rowsum[i] = 1.0f / g_rowsum[i];
}

// Pass B: out[e] *= rinv[row[e]]. 8 edges/thread, front-batched loads.
__global__ void normalize_kernel(const int* __restrict__ row,
                                 float* __restrict__ out,
                                 int E) {
    int t = blockIdx.x * blockDim.x + threadIdx.x;
    int e = t * 8;
    if (e + 7 < E) {
        int4   r0 = __ldcs(reinterpret_cast<const int4*>(row + e));
        int4   r1 = __ldcs(reinterpret_cast<const int4*>(row + e + 4));
        float4 v0 = __ldcs(reinterpret_cast<const float4*>(out + e));
        float4 v1 = __ldcs(reinterpret_cast<const float4*>(out + e + 4));

        // Gathers on default policy: g_rowsum benefits from L1/L2 residency.
        float s0 = g_rowsum[r0.x];
        float s1 = g_rowsum[r0.y];
        float s2 = g_rowsum[r0.z];
        float s3 = g_rowsum[r0.w];
        float s4 = g_rowsum[r1.x];
        float s5 = g_rowsum[r1.y];
        float s6 = g_rowsum[r1.z];
        float s7 = g_rowsum[r1.w];

        v0.x *= s0; v0.y *= s1; v0.z *= s2; v0.w *= s3;
        v1.x *= s4; v1.y *= s5; v1.z *= s6; v1.w *= s7;

        __stcs(reinterpret_cast<float4*>(out + e),     v0);
        __stcs(reinterpret_cast<float4*>(out + e + 4), v1);
    } else {
        for (int k = e; k < E; k++) {
            out[k] *= g_rowsum[row[k]];
        }
    }
}

extern "C" void kernel_launch(void* const* d_in, const int* in_sizes, int n_in,
                              void* d_out, int out_size) {
    const int*   row  = (const int*)d_in[0];   // first E of (2,E) int32
    const float* attr = (const float*)d_in[1];
    float*       out  = (float*)d_out;
    int E = in_sizes[1];

    const int T = 256;
    zero_rowsum_kernel<<<(N_NODES / 4 + T - 1) / T, T>>>();

    int e8 = (E + 7) / 8;
    int eblk = (e8 + T - 1) / T;
    scatter_kernel<<<eblk, T>>>(row, attr, out, E);

    recip_kernel<<<(N_NODES + T - 1) / T, T>>>();

    normalize_kernel<<<eblk, T>>>(row, out, E);
}

// round 15
// speedup vs baseline: 1.1407x; 1.0539x over previous
#include <cuda_runtime.h>
#include <cstdint>

// RowSoftmax over edges:
//   et  = exp(leaky_relu(attr, 0.01))
//   out = et / segment_sum(et, row)
//
// edge_index is int32 on device (JAX x64 disabled). d_in[0] = (2,E) int32,
// row = first E entries.
//
// Perf model (B300): scatter is REDG spread-addr bound (1.29 cyc/lane),
// finalize is L1tex divergent-gather bound. This round: remove the et store
// stream from scatter entirely — pass B recomputes exp(lrelu(attr)) (FMA/MUFU
// pipes are idle), so et never round-trips through DRAM.

#define N_NODES 1000000

__device__ float g_rowsum[N_NODES];  // 4 MB, L2-resident during hot passes

__global__ void zero_rowsum_kernel() {
    int i = blockIdx.x * blockDim.x + threadIdx.x;
    if (i < N_NODES / 4) {
        reinterpret_cast<float4*>(g_rowsum)[i] = make_float4(0.f, 0.f, 0.f, 0.f);
    }
}

__device__ __forceinline__ float et_of(float a) {
    float lr = a > 0.0f ? a : 0.01f * a;
    return __expf(lr);
}

// Pass A: g_rowsum[row] += exp(lrelu(attr)). 8 edges/thread, no stores.
__global__ void scatter_kernel(const int* __restrict__ row,
                               const float* __restrict__ attr,
                               int E) {
    int t = blockIdx.x * blockDim.x + threadIdx.x;
    int e = t * 8;
    if (e + 7 < E) {
        float4 a0 = __ldcs(reinterpret_cast<const float4*>(attr + e));
        float4 a1 = __ldcs(reinterpret_cast<const float4*>(attr + e + 4));
        int4   r0 = __ldcs(reinterpret_cast<const int4*>(row + e));
        int4   r1 = __ldcs(reinterpret_cast<const int4*>(row + e + 4));

        atomicAdd(&g_rowsum[r0.x], et_of(a0.x));
        atomicAdd(&g_rowsum[r0.y], et_of(a0.y));
        atomicAdd(&g_rowsum[r0.z], et_of(a0.z));
        atomicAdd(&g_rowsum[r0.w], et_of(a0.w));
        atomicAdd(&g_rowsum[r1.x], et_of(a1.x));
        atomicAdd(&g_rowsum[r1.y], et_of(a1.y));
        atomicAdd(&g_rowsum[r1.z], et_of(a1.z));
        atomicAdd(&g_rowsum[r1.w], et_of(a1.w));
    } else {
        for (int k = e; k < E; k++) {
            float lr = attr[k] > 0.0f ? attr[k] : 0.01f * attr[k];
            atomicAdd(&g_rowsum[row[k]], expf(lr));
        }
    }
}

// Invert sums in place.
__global__ void recip_kernel() {
    int i = blockIdx.x * blockDim.x + threadIdx.x;
    if (i < N_NODES) g_rowsum[i] = 1.0f / g_rowsum[i];
}

// Pass B: out[e] = exp(lrelu(attr[e])) * rinv[row[e]]. 8 edges/thread.
__global__ void finalize_kernel(const int* __restrict__ row,
                                const float* __restrict__ attr,
                                float* __restrict__ out,
                                int E) {
    int t = blockIdx.x * blockDim.x + threadIdx.x;
    int e = t * 8;
    if (e + 7 < E) {
        int4   r0 = __ldcs(reinterpret_cast<const int4*>(row + e));
        int4   r1 = __ldcs(reinterpret_cast<const int4*>(row + e + 4));
        float4 a0 = __ldcs(reinterpret_cast<const float4*>(attr + e));
        float4 a1 = __ldcs(reinterpret_cast<const float4*>(attr + e + 4));

        // Gathers on default policy: g_rowsum stays L1/L2 resident.
        float s0 = g_rowsum[r0.x];
        float s1 = g_rowsum[r0.y];
        float s2 = g_rowsum[r0.z];
        float s3 = g_rowsum[r0.w];
        float s4 = g_rowsum[r1.x];
        float s5 = g_rowsum[r1.y];
        float s6 = g_rowsum[r1.z];
        float s7 = g_rowsum[r1.w];

        float4 v0, v1;
        v0.x = et_of(a0.x) * s0;
        v0.y = et_of(a0.y) * s1;
        v0.z = et_of(a0.z) * s2;
        v0.w = et_of(a0.w) * s3;
        v1.x = et_of(a1.x) * s4;
        v1.y = et_of(a1.y) * s5;
        v1.z = et_of(a1.z) * s6;
        v1.w = et_of(a1.w) * s7;

        __stcs(reinterpret_cast<float4*>(out + e),     v0);
        __stcs(reinterpret_cast<float4*>(out + e + 4), v1);
    } else {
        for (int k = e; k < E; k++) {
            float lr = attr[k] > 0.0f ? attr[k] : 0.01f * attr[k];
            out[k] = expf(lr) * g_rowsum[row[k]];
        }
    }
}

extern "C" void kernel_launch(void* const* d_in, const int* in_sizes, int n_in,
                              void* d_out, int out_size) {
    const int*   row  = (const int*)d_in[0];   // first E of (2,E) int32
    const float* attr = (const float*)d_in[1];
    float*       out  = (float*)d_out;
    int E = in_sizes[1];

    const int T = 256;
    zero_rowsum_kernel<<<(N_NODES / 4 + T - 1) / T, T>>>();

    int e8 = (E + 7) / 8;
    int eblk = (e8 + T - 1) / T;
    scatter_kernel<<<eblk, T>>>(row, attr, E);

    recip_kernel<<<(N_NODES + T - 1) / T, T>>>();

    finalize_kernel<<<eblk, T>>>(row, attr, out, E);
}

// round 16
// speedup vs baseline: 1.1480x; 1.0063x over previous
#include <cuda_runtime.h>
#include <cstdint>

// RowSoftmax over edges:
//   et  = exp(leaky_relu(attr, 0.01))
//   out = et / segment_sum(et, row)
//
// edge_index is int32 on device (JAX x64 disabled). d_in[0] = (2,E) int32,
// row = first E entries.
//
// Perf model (B300): scatter at REDG spread-addr floor (~1.29 cyc/lane),
// finalize at L1tex divergent-gather floor. et never round-trips DRAM
// (recomputed in pass B). This round: PDL overlap of the 4-kernel chain to
// hide launch/drain boundaries (~19us of non-edge overhead).

#define N_NODES 1000000

__device__ float g_rowsum[N_NODES];  // 4 MB, L2-resident during hot passes

__global__ void zero_rowsum_kernel() {
    int i = blockIdx.x * blockDim.x + threadIdx.x;
    if (i < N_NODES / 4) {
        reinterpret_cast<float4*>(g_rowsum)[i] = make_float4(0.f, 0.f, 0.f, 0.f);
    }
}

__device__ __forceinline__ float et_of(float a) {
    float lr = a > 0.0f ? a : 0.01f * a;
    return __expf(lr);
}

// Pass A: g_rowsum[row] += exp(lrelu(attr)). 8 edges/thread, no stores.
__global__ void scatter_kernel(const int* __restrict__ row,
                               const float* __restrict__ attr,
                               int E) {
#if __CUDA_ARCH__ >= 900
    cudaGridDependencySynchronize();  // wait for zero_rowsum flush
#endif
    int t = blockIdx.x * blockDim.x + threadIdx.x;
    int e = t * 8;
    if (e + 7 < E) {
        float4 a0 = __ldcs(reinterpret_cast<const float4*>(attr + e));
        float4 a1 = __ldcs(reinterpret_cast<const float4*>(attr + e + 4));
        int4   r0 = __ldcs(reinterpret_cast<const int4*>(row + e));
        int4   r1 = __ldcs(reinterpret_cast<const int4*>(row + e + 4));

        atomicAdd(&g_rowsum[r0.x], et_of(a0.x));
        atomicAdd(&g_rowsum[r0.y], et_of(a0.y));
        atomicAdd(&g_rowsum[r0.z], et_of(a0.z));
        atomicAdd(&g_rowsum[r0.w], et_of(a0.w));
        atomicAdd(&g_rowsum[r1.x], et_of(a1.x));
        atomicAdd(&g_rowsum[r1.y], et_of(a1.y));
        atomicAdd(&g_rowsum[r1.z], et_of(a1.z));
        atomicAdd(&g_rowsum[r1.w], et_of(a1.w));
    } else {
        for (int k = e; k < E; k++) {
            float lr = attr[k] > 0.0f ? attr[k] : 0.01f * attr[k];
            atomicAdd(&g_rowsum[row[k]], expf(lr));
        }
    }
}

// Invert sums in place.
__global__ void recip_kernel() {
#if __CUDA_ARCH__ >= 900
    cudaGridDependencySynchronize();  // all scatter atomics visible
#endif
    int i = blockIdx.x * blockDim.x + threadIdx.x;
    if (i < N_NODES) g_rowsum[i] = 1.0f / g_rowsum[i];
}

// Pass B: out[e] = exp(lrelu(attr[e])) * rinv[row[e]]. 8 edges/thread.
__global__ void finalize_kernel(const int* __restrict__ row,
                                const float* __restrict__ attr,
                                float* __restrict__ out,
                                int E) {
#if __CUDA_ARCH__ >= 900
    cudaGridDependencySynchronize();  // all reciprocals visible
#endif
    int t = blockIdx.x * blockDim.x + threadIdx.x;
    int e = t * 8;
    if (e + 7 < E) {
        // Row indices + gathers first: shortens the dependent critical path.
        int4 r0 = __ldcs(reinterpret_cast<const int4*>(row + e));
        int4 r1 = __ldcs(reinterpret_cast<const int4*>(row + e + 4));

        float s0 = g_rowsum[r0.x];
        float s1 = g_rowsum[r0.y];
        float s2 = g_rowsum[r0.z];
        float s3 = g_rowsum[r0.w];
        float s4 = g_rowsum[r1.x];
        float s5 = g_rowsum[r1.y];
        float s6 = g_rowsum[r1.z];
        float s7 = g_rowsum[r1.w];

        float4 a0 = __ldcs(reinterpret_cast<const float4*>(attr + e));
        float4 a1 = __ldcs(reinterpret_cast<const float4*>(attr + e + 4));

        float4 v0, v1;
        v0.x = et_of(a0.x) * s0;
        v0.y = et_of(a0.y) * s1;
        v0.z = et_of(a0.z) * s2;
        v0.w = et_of(a0.w) * s3;
        v1.x = et_of(a1.x) * s4;
        v1.y = et_of(a1.y) * s5;
        v1.z = et_of(a1.z) * s6;
        v1.w = et_of(a1.w) * s7;

        __stcs(reinterpret_cast<float4*>(out + e),     v0);
        __stcs(reinterpret_cast<float4*>(out + e + 4), v1);
    } else {
        for (int k = e; k < E; k++) {
            float lr = attr[k] > 0.0f ? attr[k] : 0.01f * attr[k];
            out[k] = expf(lr) * g_rowsum[row[k]];
        }
    }
}

// Launch helper: PDL-enabled launch on the capture (legacy default) stream.
template <typename K, typename... Args>
static void launch_pdl(K kernel, dim3 grid, dim3 block, Args... args) {
    cudaLaunchAttribute attr[1];
    attr[0].id = cudaLaunchAttributeProgrammaticStreamSerialization;
    attr[0].val.programmaticStreamSerializationAllowed = 1;
    cudaLaunchConfig_t cfg{};
    cfg.gridDim = grid;
    cfg.blockDim = block;
    cfg.dynamicSmemBytes = 0;
    cfg.stream = 0;  // legacy default stream (the one being captured)
    cfg.attrs = attr;
    cfg.numAttrs = 1;
    cudaLaunchKernelEx(&cfg, kernel, args...);
}

extern "C" void kernel_launch(void* const* d_in, const int* in_sizes, int n_in,
                              void* d_out, int out_size) {
    const int*   row  = (const int*)d_in[0];   // first E of (2,E) int32
    const float* attr = (const float*)d_in[1];
    float*       out  = (float*)d_out;
    int E = in_sizes[1];

    const int T = 256;
    zero_rowsum_kernel<<<(N_NODES / 4 + T - 1) / T, T>>>();

    int e8 = (E + 7) / 8;
    dim3 eblk((e8 + T - 1) / T);
    launch_pdl(scatter_kernel, eblk, dim3(T), row, attr, E);

    launch_pdl(recip_kernel, dim3((N_NODES + T - 1) / T), dim3(T));

    launch_pdl(finalize_kernel, eblk, dim3(T), row, attr, out, E);
}

// round 17
// speedup vs baseline: 1.1571x; 1.0080x over previous
#include <cuda_runtime.h>
#include <cstdint>

// RowSoftmax over edges:
//   et  = exp(leaky_relu(attr, 0.01))
//   out = et / segment_sum(et, row)
//
// edge_index is int32 on device (JAX x64 disabled). d_in[0] = (2,E) int32,
// row = first E entries.
//
// Perf model (B300): scatter at REDG spread-addr floor (~1.29 cyc/lane),
// finalize at L1tex divergent-gather floor. et recomputed in pass B (no DRAM
// round-trip). This round: recip kernel fused into finalize via __fdividef
// (1.05M warp-RCPs ~ 8us of MUFU, hidden under the LSU-bound body).

#define N_NODES 1000000

__device__ float g_rowsum[N_NODES];  // 4 MB, L2-resident during hot passes

__global__ void zero_rowsum_kernel() {
    int i = blockIdx.x * blockDim.x + threadIdx.x;
    if (i < N_NODES / 4) {
        reinterpret_cast<float4*>(g_rowsum)[i] = make_float4(0.f, 0.f, 0.f, 0.f);
    }
}

__device__ __forceinline__ float et_of(float a) {
    float lr = a > 0.0f ? a : 0.01f * a;
    return __expf(lr);
}

// Pass A: g_rowsum[row] += exp(lrelu(attr)). 8 edges/thread, no stores.
__global__ void scatter_kernel(const int* __restrict__ row,
                               const float* __restrict__ attr,
                               int E) {
#if __CUDA_ARCH__ >= 900
    cudaGridDependencySynchronize();  // wait for zero_rowsum flush
#endif
    int t = blockIdx.x * blockDim.x + threadIdx.x;
    int e = t * 8;
    if (e + 7 < E) {
        float4 a0 = __ldcs(reinterpret_cast<const float4*>(attr + e));
        float4 a1 = __ldcs(reinterpret_cast<const float4*>(attr + e + 4));
        int4   r0 = __ldcs(reinterpret_cast<const int4*>(row + e));
        int4   r1 = __ldcs(reinterpret_cast<const int4*>(row + e + 4));

        atomicAdd(&g_rowsum[r0.x], et_of(a0.x));
        atomicAdd(&g_rowsum[r0.y], et_of(a0.y));
        atomicAdd(&g_rowsum[r0.z], et_of(a0.z));
        atomicAdd(&g_rowsum[r0.w], et_of(a0.w));
        atomicAdd(&g_rowsum[r1.x], et_of(a1.x));
        atomicAdd(&g_rowsum[r1.y], et_of(a1.y));
        atomicAdd(&g_rowsum[r1.z], et_of(a1.z));
        atomicAdd(&g_rowsum[r1.w], et_of(a1.w));
    } else {
        for (int k = e; k < E; k++) {
            float lr = attr[k] > 0.0f ? attr[k] : 0.01f * attr[k];
            atomicAdd(&g_rowsum[row[k]], expf(lr));
        }
    }
}

// Pass B: out[e] = exp(lrelu(attr[e])) / rowsum[row[e]]. 8 edges/thread.
// Division fused via fast reciprocal (MUFU.RCP hidden under LSU-bound body).
__global__ void finalize_kernel(const int* __restrict__ row,
                                const float* __restrict__ attr,
                                float* __restrict__ out,
                                int E) {
#if __CUDA_ARCH__ >= 900
    cudaGridDependencySynchronize();  // all scatter atomics visible
#endif
    int t = blockIdx.x * blockDim.x + threadIdx.x;
    int e = t * 8;
    if (e + 7 < E) {
        // Row indices + gathers first: longest-latency chain starts earliest.
        int4 r0 = __ldcs(reinterpret_cast<const int4*>(row + e));
        int4 r1 = __ldcs(reinterpret_cast<const int4*>(row + e + 4));

        float s0 = g_rowsum[r0.x];
        float s1 = g_rowsum[r0.y];
        float s2 = g_rowsum[r0.z];
        float s3 = g_rowsum[r0.w];
        float s4 = g_rowsum[r1.x];
        float s5 = g_rowsum[r1.y];
        float s6 = g_rowsum[r1.z];
        float s7 = g_rowsum[r1.w];

        float4 a0 = __ldcs(reinterpret_cast<const float4*>(attr + e));
        float4 a1 = __ldcs(reinterpret_cast<const float4*>(attr + e + 4));

        float4 v0, v1;
        v0.x = __fdividef(et_of(a0.x), s0);
        v0.y = __fdividef(et_of(a0.y), s1);
        v0.z = __fdividef(et_of(a0.z), s2);
        v0.w = __fdividef(et_of(a0.w), s3);
        v1.x = __fdividef(et_of(a1.x), s4);
        v1.y = __fdividef(et_of(a1.y), s5);
        v1.z = __fdividef(et_of(a1.z), s6);
        v1.w = __fdividef(et_of(a1.w), s7);

        __stcs(reinterpret_cast<float4*>(out + e),     v0);
        __stcs(reinterpret_cast<float4*>(out + e + 4), v1);
    } else {
        for (int k = e; k < E; k++) {
            float lr = attr[k] > 0.0f ? attr[k] : 0.01f * attr[k];
            out[k] = __fdividef(expf(lr), g_rowsum[row[k]]);
        }
    }
}

// Launch helper: PDL-enabled launch on the capture (legacy default) stream.
template <typename K, typename... Args>
static void launch_pdl(K kernel, dim3 grid, dim3 block, Args... args) {
    cudaLaunchAttribute attr[1];
    attr[0].id = cudaLaunchAttributeProgrammaticStreamSerialization;
    attr[0].val.programmaticStreamSerializationAllowed = 1;
    cudaLaunchConfig_t cfg{};
    cfg.gridDim = grid;
    cfg.blockDim = block;
    cfg.dynamicSmemBytes = 0;
    cfg.stream = 0;  // legacy default stream (the one being captured)
    cfg.attrs = attr;
    cfg.numAttrs = 1;
    cudaLaunchKernelEx(&cfg, kernel, args...);
}

extern "C" void kernel_launch(void* const* d_in, const int* in_sizes, int n_in,
                              void* d_out, int out_size) {
    const int*   row  = (const int*)d_in[0];   // first E of (2,E) int32
    const float* attr = (const float*)d_in[1];
    float*       out  = (float*)d_out;
    int E = in_sizes[1];

    const int T = 256;
    zero_rowsum_kernel<<<(N_NODES / 4 + T - 1) / T, T>>>();

    int e8 = (E + 7) / 8;
    dim3 eblk((e8 + T - 1) / T);
    launch_pdl(scatter_kernel, eblk, dim3(T), row, attr, E);

    launch_pdl(finalize_kernel, eblk, dim3(T), row, attr, out, E);
}